// round 3
// baseline (speedup 1.0000x reference)
#include <cuda_runtime.h>

#define HH 768
#define WW 768
#define CC 64
#define NSEG 385   // max segments per axis: 384 rising edges + segment 0

// ---- scratch (device globals; no allocations allowed) ----
__device__ int   g_row_id[HH];
__device__ int   g_col_id[WW];
__device__ int   g_row_start[NSEG + 1];
__device__ int   g_col_start[NSEG + 1];
__device__ int   g_nrow;
__device__ int   g_ncol;
__device__ float g_cellmean[(size_t)NSEG * NSEG * CC];   // ~38 MB

// ---------------------------------------------------------------------------
// Kernel 1: segment ids + segment start offsets for both masks.
// block 0 -> h_mask (rows), block 1 -> v_mask (cols). 768 threads.
// rising edge: m[i]==1 && m[i-1]==0, i>0. seg id = inclusive scan of rising.
// ---------------------------------------------------------------------------
__global__ void seg_kernel(const int* __restrict__ h_mask,
                           const int* __restrict__ v_mask) {
    __shared__ int sm[HH];
    __shared__ int wsum[24];

    const int b = blockIdx.x;
    const int* m   = (b == 0) ? h_mask : v_mask;
    int* seg       = (b == 0) ? g_row_id : g_col_id;
    int* start     = (b == 0) ? g_row_start : g_col_start;

    const int t = threadIdx.x;
    const int mv = m[t];
    sm[t] = mv;
    __syncthreads();

    const int rise = (t > 0 && mv == 1 && sm[t - 1] == 0) ? 1 : 0;

    // inclusive scan of `rise` across 768 threads (24 warps)
    const int lane = t & 31, w = t >> 5;
    int v = rise;
    #pragma unroll
    for (int o = 1; o < 32; o <<= 1) {
        int n = __shfl_up_sync(0xFFFFFFFFu, v, o);
        if (lane >= o) v += n;
    }
    if (lane == 31) wsum[w] = v;
    __syncthreads();
    if (w == 0) {
        int ws = (lane < 24) ? wsum[lane] : 0;
        #pragma unroll
        for (int o = 1; o < 32; o <<= 1) {
            int n = __shfl_up_sync(0xFFFFFFFFu, ws, o);
            if (lane >= o) ws += n;
        }
        if (lane < 24) wsum[lane] = ws;
    }
    __syncthreads();
    const int sid = v + ((w > 0) ? wsum[w - 1] : 0);

    seg[t] = sid;
    if (rise) start[sid] = t;        // new segment starts here
    if (t == 0) start[0] = 0;
    if (t == (HH - 1)) {
        start[sid + 1] = HH;
        if (b == 0) g_nrow = sid + 1; else g_ncol = sid + 1;
    }
}

// ---------------------------------------------------------------------------
// Kernel 2: per-cell mean, one block per (rseg, cseg) rectangle.
// 64 threads = 64 channels -> every (y,x) read is one fully-coalesced 256B txn.
// Grid is the static upper bound (385x385); excess blocks exit on the guard.
// ---------------------------------------------------------------------------
__global__ void cell_mean_kernel(const float* __restrict__ in) {
    const int cseg = blockIdx.x;
    const int rseg = blockIdx.y;
    if (cseg >= g_ncol || rseg >= g_nrow) return;

    const int cs = g_col_start[cseg], ce = g_col_start[cseg + 1];
    const int rs = g_row_start[rseg], re = g_row_start[rseg + 1];
    const int ch = threadIdx.x;

    float acc = 0.f;
    for (int y = rs; y < re; ++y) {
        const float* rowp = in + ((size_t)y * WW) * CC + ch;
        #pragma unroll 4
        for (int x = cs; x < ce; ++x)
            acc += __ldg(rowp + (size_t)x * CC);
    }
    const float inv = 1.0f / (float)((re - rs) * (ce - cs));
    g_cellmean[((size_t)rseg * NSEG + cseg) * CC + ch] = acc * inv;
}

// ---------------------------------------------------------------------------
// Kernel 3: broadcast cell means back to all pixels, float4 stores.
// idx covers H*W*(C/4) float4 elements; 16 float4 per pixel.
// ---------------------------------------------------------------------------
__global__ void broadcast_kernel(float4* __restrict__ out) {
    const int idx = blockIdx.x * blockDim.x + threadIdx.x;  // < H*W*16
    const int q = idx & 15;
    const int p = idx >> 4;
    const int y = p / WW;
    const int x = p - y * WW;
    const int cell = g_row_id[y] * NSEG + g_col_id[x];
    const float4* cm = reinterpret_cast<const float4*>(g_cellmean);
    out[idx] = __ldg(&cm[(size_t)cell * 16 + q]);
}

// ---------------------------------------------------------------------------
extern "C" void kernel_launch(void* const* d_in, const int* in_sizes, int n_in,
                              void* d_out, int out_size) {
    const float* in = (const float*)d_in[0];
    const int*   hm = (const int*)d_in[1];
    const int*   vm = (const int*)d_in[2];
    float*       out = (float*)d_out;

    seg_kernel<<<2, HH>>>(hm, vm);
    cell_mean_kernel<<<dim3(NSEG, NSEG), CC>>>(in);

    const int total4 = HH * WW * (CC / 4);   // 9,437,184
    broadcast_kernel<<<total4 / 256, 256>>>(reinterpret_cast<float4*>(out));
}

// round 6
// speedup vs baseline: 1.2783x; 1.2783x over previous
#include <cuda_runtime.h>

#define HH 768
#define WW 768
#define CC 64
#define NSEG 385   // max segments per axis: 384 rising edges + segment 0

// ---- scratch (device globals; no allocations allowed) ----
__device__ int   g_row_id[HH];
__device__ int   g_col_id[WW];
__device__ int   g_row_start[NSEG + 1];
__device__ int   g_col_start[NSEG + 1];
__device__ int   g_nrow;
__device__ int   g_ncol;
__device__ float g_cellmean[(size_t)NSEG * NSEG * CC];   // compact-indexed; ~9.4MB used

// ---------------------------------------------------------------------------
// Kernel 1: segment ids + segment start offsets for both masks.
// block 0 -> h_mask (rows), block 1 -> v_mask (cols). 768 threads.
// ---------------------------------------------------------------------------
__global__ void seg_kernel(const int* __restrict__ h_mask,
                           const int* __restrict__ v_mask) {
    __shared__ int sm[HH];
    __shared__ int wsum[24];

    const int b = blockIdx.x;
    const int* m   = (b == 0) ? h_mask : v_mask;
    int* seg       = (b == 0) ? g_row_id : g_col_id;
    int* start     = (b == 0) ? g_row_start : g_col_start;

    const int t = threadIdx.x;
    const int mv = m[t];
    sm[t] = mv;
    __syncthreads();

    const int rise = (t > 0 && mv == 1 && sm[t - 1] == 0) ? 1 : 0;

    // inclusive scan of `rise` across 768 threads (24 warps)
    const int lane = t & 31, w = t >> 5;
    int v = rise;
    #pragma unroll
    for (int o = 1; o < 32; o <<= 1) {
        int n = __shfl_up_sync(0xFFFFFFFFu, v, o);
        if (lane >= o) v += n;
    }
    if (lane == 31) wsum[w] = v;
    __syncthreads();
    if (w == 0) {
        int ws = (lane < 24) ? wsum[lane] : 0;
        #pragma unroll
        for (int o = 1; o < 32; o <<= 1) {
            int n = __shfl_up_sync(0xFFFFFFFFu, ws, o);
            if (lane >= o) ws += n;
        }
        if (lane < 24) wsum[lane] = ws;
    }
    __syncthreads();
    const int sid = v + ((w > 0) ? wsum[w - 1] : 0);

    seg[t] = sid;
    if (rise) start[sid] = t;
    if (t == 0) start[0] = 0;
    if (t == (HH - 1)) {
        start[sid + 1] = HH;
        if (b == 0) g_nrow = sid + 1; else g_ncol = sid + 1;
    }
}

// ---------------------------------------------------------------------------
// Kernel 2: per-cell mean, grid-stride over COMPACT cell ids (no dead blocks).
// 64 threads: lane bits [0:2] = x sub-offset (4-wide x parallelism),
//             bits [2:6]      = channel quad (float4), 16 quads = 64 channels.
// Per-(y,x-quad) the block issues 4 x-positions x 16B float4 loads in flight.
// Reduce over the 4 x-offsets with shfl (they sit in adjacent lanes).
// ---------------------------------------------------------------------------
__global__ void __launch_bounds__(64) cell_mean_kernel(const float* __restrict__ in) {
    const int nrow = g_nrow;
    const int ncol = g_ncol;
    const int total = nrow * ncol;

    const int xo = threadIdx.x & 3;     // x offset within group of 4
    const int cg = threadIdx.x >> 2;    // channel quad 0..15

    for (int cell = blockIdx.x; cell < total; cell += gridDim.x) {
        const int rseg = cell / ncol;
        const int cseg = cell - rseg * ncol;
        const int cs = g_col_start[cseg], ce = g_col_start[cseg + 1];
        const int rs = g_row_start[rseg], re = g_row_start[rseg + 1];

        float4 acc = make_float4(0.f, 0.f, 0.f, 0.f);
        for (int y = rs; y < re; ++y) {
            const float4* rowp = reinterpret_cast<const float4*>(
                in + (size_t)y * WW * CC);           // [WW][16] float4
            #pragma unroll 2
            for (int x = cs + xo; x < ce; x += 4) {
                float4 v = __ldg(&rowp[x * 16 + cg]);
                acc.x += v.x; acc.y += v.y; acc.z += v.z; acc.w += v.w;
            }
        }
        // reduce across the 4 x-offset lanes (aligned groups of 4 lanes)
        #pragma unroll
        for (int o = 1; o < 4; o <<= 1) {
            acc.x += __shfl_down_sync(0xFFFFFFFFu, acc.x, o);
            acc.y += __shfl_down_sync(0xFFFFFFFFu, acc.y, o);
            acc.z += __shfl_down_sync(0xFFFFFFFFu, acc.z, o);
            acc.w += __shfl_down_sync(0xFFFFFFFFu, acc.w, o);
        }
        if (xo == 0) {
            const float inv = 1.0f / (float)((re - rs) * (ce - cs));
            float4 r = make_float4(acc.x * inv, acc.y * inv, acc.z * inv, acc.w * inv);
            reinterpret_cast<float4*>(g_cellmean)[(size_t)cell * 16 + cg] = r;
        }
    }
}

// ---------------------------------------------------------------------------
// Kernel 3: broadcast cell means back to all pixels, float4 stores.
// Compact cell id = row_id[y]*ncol + col_id[x] -> 9.4MB gather, L2-resident.
// ---------------------------------------------------------------------------
__global__ void broadcast_kernel(float4* __restrict__ out) {
    const int idx = blockIdx.x * blockDim.x + threadIdx.x;  // < H*W*16
    const int q = idx & 15;
    const int p = idx >> 4;
    const int y = p / WW;
    const int x = p - y * WW;
    const int ncol = g_ncol;
    const int cell = __ldg(&g_row_id[y]) * ncol + __ldg(&g_col_id[x]);
    const float4* cm = reinterpret_cast<const float4*>(g_cellmean);
    out[idx] = __ldg(&cm[(size_t)cell * 16 + q]);
}

// ---------------------------------------------------------------------------
extern "C" void kernel_launch(void* const* d_in, const int* in_sizes, int n_in,
                              void* d_out, int out_size) {
    const float* in = (const float*)d_in[0];
    const int*   hm = (const int*)d_in[1];
    const int*   vm = (const int*)d_in[2];
    float*       out = (float*)d_out;

    seg_kernel<<<2, HH>>>(hm, vm);
    cell_mean_kernel<<<148 * 32, 64>>>(in);   // grid-stride over compact cells

    const int total4 = HH * WW * (CC / 4);    // 9,437,184
    broadcast_kernel<<<total4 / 256, 256>>>(reinterpret_cast<float4*>(out));
}

// round 7
// speedup vs baseline: 1.5378x; 1.2030x over previous
#include <cuda_runtime.h>

#define HH 768
#define WW 768
#define CC 64
#define NSEG 385            // max segments per axis
#define NTHREADS 64
#define PER_T (HH / NTHREADS)   // 12 mask elems per thread
#define GRID_BLOCKS (148 * 32)  // one full wave on GB300 (152 SMs; 148 conservative)

// ---------------------------------------------------------------------------
// Single fused kernel:
//  prolog: every block redundantly scans both masks -> row/col segment starts
//          in SMEM (1536 L2-broadcast int loads + 64-thread scan, ~0.5us,
//          paid once per block, all blocks concurrent = one wave).
//  main:   grid-stride over compact cells (rseg,cseg). Each block:
//            - sums its rectangle (float4 loads, y-unrolled x2 for MLP)
//            - xor-shuffle reduce across the 4 x-offset lanes (all lanes get sum)
//            - writes the mean back to every pixel of the rectangle (float4)
//  Traffic: 151MB read + 151MB write, nothing else. No inter-kernel deps.
// ---------------------------------------------------------------------------
__global__ void __launch_bounds__(NTHREADS)
fused_grid_pool(const float* __restrict__ in,
                const int* __restrict__ h_mask,
                const int* __restrict__ v_mask,
                float* __restrict__ out) {
    __shared__ int s_row_start[NSEG + 1];
    __shared__ int s_col_start[NSEG + 1];
    __shared__ int s_tmp[2];
    __shared__ int s_nrow, s_ncol;

    const int t = threadIdx.x;
    const int lane = t & 31, w = t >> 5;

    // ---- prolog: build segment starts for both masks ----
    #pragma unroll
    for (int axis = 0; axis < 2; ++axis) {
        const int* m = (axis == 0) ? h_mask : v_mask;
        int* start   = (axis == 0) ? s_row_start : s_col_start;

        const int base = t * PER_T;
        int pm = (base == 0) ? 1 : m[base - 1];   // pm=1 at i=0 forces rise[0]=0
        int rises = 0, cnt = 0;                    // bitmask of rises in chunk
        #pragma unroll
        for (int k = 0; k < PER_T; ++k) {
            const int mv = m[base + k];
            const int r = (mv == 1 && pm == 0);
            rises |= (r << k);
            cnt += r;
            pm = mv;
        }
        // exclusive scan of cnt across 64 threads (2 warps)
        int v = cnt;
        #pragma unroll
        for (int o = 1; o < 32; o <<= 1) {
            int n = __shfl_up_sync(0xFFFFFFFFu, v, o);
            if (lane >= o) v += n;
        }
        if (lane == 31) s_tmp[w] = v;
        __syncthreads();
        const int add   = (w == 1) ? s_tmp[0] : 0;
        const int total = s_tmp[0] + s_tmp[1];
        const int excl  = v + add - cnt;

        int sid = excl;
        #pragma unroll
        for (int k = 0; k < PER_T; ++k) {
            if ((rises >> k) & 1) { ++sid; start[sid] = base + k; }
        }
        const int nseg = total + 1;
        if (t == 0) { start[0] = 0; start[nseg] = HH; }
        if (t == 0) { if (axis == 0) s_nrow = nseg; else s_ncol = nseg; }
        __syncthreads();
    }

    const int nrow = s_nrow, ncol = s_ncol;
    const int total_cells = nrow * ncol;

    const int xo = t & 3;     // x offset within group of 4
    const int cg = t >> 2;    // channel quad 0..15

    // ---- main: grid-stride over compact cells ----
    for (int cell = blockIdx.x; cell < total_cells; cell += GRID_BLOCKS) {
        const int rseg = cell / ncol;
        const int cseg = cell - rseg * ncol;
        const int cs = s_col_start[cseg], ce = s_col_start[cseg + 1];
        const int rs = s_row_start[rseg], re = s_row_start[rseg + 1];

        float4 a0 = make_float4(0.f, 0.f, 0.f, 0.f);
        float4 a1 = make_float4(0.f, 0.f, 0.f, 0.f);

        int y = rs;
        for (; y + 1 < re; y += 2) {
            const float4* r0 = reinterpret_cast<const float4*>(
                in + (size_t)y * WW * CC);
            const float4* r1 = r0 + WW * (CC / 4);
            for (int x = cs + xo; x < ce; x += 4) {
                const float4 v0 = __ldg(&r0[x * 16 + cg]);
                const float4 v1 = __ldg(&r1[x * 16 + cg]);
                a0.x += v0.x; a0.y += v0.y; a0.z += v0.z; a0.w += v0.w;
                a1.x += v1.x; a1.y += v1.y; a1.z += v1.z; a1.w += v1.w;
            }
        }
        if (y < re) {
            const float4* r0 = reinterpret_cast<const float4*>(
                in + (size_t)y * WW * CC);
            for (int x = cs + xo; x < ce; x += 4) {
                const float4 v0 = __ldg(&r0[x * 16 + cg]);
                a0.x += v0.x; a0.y += v0.y; a0.z += v0.z; a0.w += v0.w;
            }
        }
        a0.x += a1.x; a0.y += a1.y; a0.z += a1.z; a0.w += a1.w;

        // xor-reduce across the 4 x-offset lanes -> every lane holds full sum
        #pragma unroll
        for (int o = 1; o < 4; o <<= 1) {
            a0.x += __shfl_xor_sync(0xFFFFFFFFu, a0.x, o);
            a0.y += __shfl_xor_sync(0xFFFFFFFFu, a0.y, o);
            a0.z += __shfl_xor_sync(0xFFFFFFFFu, a0.z, o);
            a0.w += __shfl_xor_sync(0xFFFFFFFFu, a0.w, o);
        }
        const float inv = 1.0f / (float)((re - rs) * (ce - cs));
        const float4 mv = make_float4(a0.x * inv, a0.y * inv, a0.z * inv, a0.w * inv);

        // broadcast: write mean to every pixel of the rectangle
        for (int y2 = rs; y2 < re; ++y2) {
            float4* ro = reinterpret_cast<float4*>(out + (size_t)y2 * WW * CC);
            for (int x = cs + xo; x < ce; x += 4)
                ro[x * 16 + cg] = mv;
        }
    }
}

// ---------------------------------------------------------------------------
extern "C" void kernel_launch(void* const* d_in, const int* in_sizes, int n_in,
                              void* d_out, int out_size) {
    const float* in = (const float*)d_in[0];
    const int*   hm = (const int*)d_in[1];
    const int*   vm = (const int*)d_in[2];
    float*       out = (float*)d_out;

    fused_grid_pool<<<GRID_BLOCKS, NTHREADS>>>(in, hm, vm, out);
}